// round 3
// baseline (speedup 1.0000x reference)
#include <cuda_runtime.h>

#define NB 128
#define NT 1024
#define ND 3
#define NH 512
#define NC 3
#define NSLICE 16      // h-slices per batch group (CTAs that must sync)
#define HS 32          // h per slice
#define NGRP 8         // batch groups
#define BGr 16         // batch rows per group
#define KS 32          // k per k-slice (per warp)
#define NKS 16         // k-slices = warps
#define THREADS 512

typedef unsigned long long u64;

// per-(group, step) arrival counters; zeroed by a kernel at every launch
__device__ int g_cnt[NGRP * NT];

static __device__ __forceinline__ u64 pack2(float x, float y) {
    u64 v; asm("mov.b64 %0, {%1, %2};" : "=l"(v) : "f"(x), "f"(y)); return v;
}
static __device__ __forceinline__ float2 unpack2(u64 v) {
    float2 f; asm("mov.b64 {%0, %1}, %2;" : "=f"(f.x), "=f"(f.y) : "l"(v)); return f;
}
static __device__ __forceinline__ u64 ffma2(u64 a, u64 b, u64 c) {
    u64 d; asm("fma.rn.f32x2 %0, %1, %2, %3;" : "=l"(d) : "l"(a), "l"(b), "l"(c)); return d;
}
static __device__ __forceinline__ u64 fadd2(u64 a, u64 b) {
    u64 d; asm("add.rn.f32x2 %0, %1, %2;" : "=l"(d) : "l"(a), "l"(b)); return d;
}

__global__ void zero_cnt_kernel() {
    int i = blockIdx.x * blockDim.x + threadIdx.x;
    if (i < NGRP * NT) g_cnt[i] = 0;
}

extern __shared__ u64 smem_u64[];

// Persistent recurrence kernel.
// blockIdx: grp = bid/16 (batch group of 16 rows), slice = bid%16 (h-slice of 32).
// Thread roles:
//   compute phase: (ks = tid>>5, hh = tid&31) — warp owns k-slice, lane owns h.
//                  Weights (Wz,W) interleaved pairs live in 64 registers/thread.
//   reduce phase:  (rb = tid>>5, hh = tid&31) — thread owns output (batch rb, h hh).
__global__ void __launch_bounds__(THREADS, 1)
flipflop_main(const float* __restrict__ inputs,
              const float* __restrict__ Wv,
              const float* __restrict__ Pv,
              const float* __restrict__ bv,
              const float* __restrict__ Wz,
              const float* __restrict__ Pz,
              const float* __restrict__ bz,
              float* __restrict__ hidden)
{
    u64* r2   = smem_u64;               // [BGr*NH]  r duplicated pairs (r,r)  = 64 KB
    u64* psum = smem_u64 + BGr * NH;    // [BGr*NKS*HS] partial (z,v) sums     = 64 KB

    const int tid   = threadIdx.x;
    const int grp   = blockIdx.x >> 4;
    const int slice = blockIdx.x & 15;
    const int ks    = tid >> 5;
    const int hh    = tid & 31;
    const int hg    = slice * HS + hh;       // global h for this lane
    const int gb    = grp * BGr;             // first global batch row of group

    // ---- load this thread's weight slice into registers (interleaved z/v) ----
    u64 w[KS];
    {
        const float4* wzr = (const float4*)(Wz + (size_t)hg * NH + ks * KS);
        const float4* wvr = (const float4*)(Wv + (size_t)hg * NH + ks * KS);
        #pragma unroll
        for (int j = 0; j < 8; ++j) {
            float4 az = wzr[j], av = wvr[j];
            w[j*4+0] = pack2(az.x, av.x);
            w[j*4+1] = pack2(az.y, av.y);
            w[j*4+2] = pack2(az.z, av.z);
            w[j*4+3] = pack2(az.w, av.w);
        }
    }

    // ---- reduce-role constants ----
    const int rb = tid >> 5;   // batch row within group (reduce/epilogue role)
    const float pz0 = Pz[hg*3+0], pz1 = Pz[hg*3+1], pz2 = Pz[hg*3+2];
    float pm0 = 0.f, pm1 = 0.f, pm2 = 0.f;        // P_m: bottom half zeroed
    if (hg < NH/2) { pm0 = Pv[hg*3+0]; pm1 = Pv[hg*3+1]; pm2 = Pv[hg*3+2]; }
    const float bzr = bz[hg];
    const float bvr = bv[hg];

    // r0 = 0
    for (int i = tid; i < BGr * NH; i += THREADS) r2[i] = 0ull;
    __syncthreads();

    const float* xrow = inputs + (size_t)(gb + rb) * NT * ND;
    float*       hrow = hidden + (size_t)(gb + rb) * NT * NH;

    for (int t = 0; t < NT; ++t) {
        // prefetch x_t for this thread's reduce row (latency hidden by compute)
        const float x0 = xrow[t*3+0], x1 = xrow[t*3+1], x2 = xrow[t*3+2];

        // ---- compute: partial (z,v) dot-products over this warp's k-slice ----
        #pragma unroll 2
        for (int b = 0; b < BGr; ++b) {
            const u64* rbv = r2 + b * NH + ks * KS;
            u64 a0 = 0ull, a1 = 0ull;
            #pragma unroll
            for (int kk = 0; kk < 16; ++kk) {
                ulonglong2 rv = *(const ulonglong2*)(rbv + kk * 2);   // (r,r),(r,r)
                a0 = ffma2(rv.x, w[kk*2+0], a0);
                a1 = ffma2(rv.y, w[kk*2+1], a1);
            }
            psum[(b * NKS + ks) * HS + hh] = fadd2(a0, a1);
        }
        __syncthreads();

        // ---- reduce + gates: thread owns (rb, hg) ----
        float sz = 0.f, sv = 0.f;
        #pragma unroll
        for (int k = 0; k < NKS; ++k) {
            float2 p = unpack2(psum[(rb * NKS + k) * HS + hh]);
            sz += p.x; sv += p.y;
        }
        const float az = sz + x0*pz0 + x1*pz1 + x2*pz2 + bzr;
        const float av = sv + x0*pm0 + x1*pm1 + x2*pm2 + bvr;
        const float z  = 1.f / (1.f + __expf(-az));
        const float c  = 1.f / (1.f + __expf(-av));
        const float ro = unpack2(r2[rb * NH + hg]).x;
        const float rn = fmaf(z, c - ro, ro);
        hrow[(size_t)t * NH + hg] = rn;        // output AND cross-CTA exchange

        if (t + 1 < NT) {
            __threadfence();
            __syncthreads();
            if (tid == 0) {
                const int idx = grp * NT + t;
                atomicAdd(&g_cnt[idx], 1);
                volatile int* pc = &g_cnt[idx];
                while (*pc < NSLICE) { }
                __threadfence();
            }
            __syncthreads();
            // reload full r(t) (all 16 slices) from hidden, store duplicated
            {
                const float4* src = (const float4*)(hidden + ((size_t)(gb + rb) * NT + t) * NH);
                #pragma unroll
                for (int j = 0; j < 4; ++j) {
                    const int p4 = hh + j * 32;
                    float4 v = src[p4];
                    u64* dst = r2 + rb * NH + p4 * 4;
                    dst[0] = pack2(v.x, v.x);
                    dst[1] = pack2(v.y, v.y);
                    dst[2] = pack2(v.z, v.z);
                    dst[3] = pack2(v.w, v.w);
                }
            }
            __syncthreads();
        }
    }
}

// out[b,t,:] = hidden[b,t,:] @ fc_W^T + fc_b   (memory-bound, ~256 MB read)
__global__ void fc_kernel(const float* __restrict__ hidden,
                          const float* __restrict__ fcW,
                          const float* __restrict__ fcb,
                          float* __restrict__ out)
{
    __shared__ float4 fw[NC][NH/4];
    __shared__ float  fb[4];
    const int tid = threadIdx.x;
    for (int i = tid; i < NC * NH / 4; i += blockDim.x)
        ((float4*)fw)[i] = ((const float4*)fcW)[i];
    if (tid < NC) fb[tid] = fcb[tid];
    __syncthreads();

    const int lane = tid & 31;
    const size_t row = (size_t)blockIdx.x * 8 + (tid >> 5);   // row in [0, B*T)
    const float4* hp = (const float4*)(hidden + row * NH);

    float a0 = 0.f, a1 = 0.f, a2 = 0.f;
    #pragma unroll
    for (int j = 0; j < 4; ++j) {
        const int i = lane + j * 32;
        float4 h4 = hp[i];
        float4 w0 = fw[0][i], w1 = fw[1][i], w2 = fw[2][i];
        a0 += h4.x*w0.x + h4.y*w0.y + h4.z*w0.z + h4.w*w0.w;
        a1 += h4.x*w1.x + h4.y*w1.y + h4.z*w1.z + h4.w*w1.w;
        a2 += h4.x*w2.x + h4.y*w2.y + h4.z*w2.z + h4.w*w2.w;
    }
    #pragma unroll
    for (int o = 16; o; o >>= 1) {
        a0 += __shfl_down_sync(0xffffffffu, a0, o);
        a1 += __shfl_down_sync(0xffffffffu, a1, o);
        a2 += __shfl_down_sync(0xffffffffu, a2, o);
    }
    if (lane == 0) {
        out[row * 3 + 0] = a0 + fb[0];
        out[row * 3 + 1] = a1 + fb[1];
        out[row * 3 + 2] = a2 + fb[2];
    }
}

extern "C" void kernel_launch(void* const* d_in, const int* in_sizes, int n_in,
                              void* d_out, int out_size)
{
    const float* inputs = (const float*)d_in[0];
    const float* Wv     = (const float*)d_in[1];
    const float* Pv     = (const float*)d_in[2];
    const float* b_v    = (const float*)d_in[3];
    const float* Wz     = (const float*)d_in[4];
    const float* Pz     = (const float*)d_in[5];
    const float* b_z    = (const float*)d_in[6];
    const float* fcW    = (const float*)d_in[7];
    const float* fcb    = (const float*)d_in[8];

    // outputs concatenated in reference return order: out (B,T,C) then hidden (B,T,H)
    float* out    = (float*)d_out;
    float* hidden = out + (size_t)NB * NT * NC;

    cudaFuncSetAttribute(flipflop_main,
                         cudaFuncAttributeMaxDynamicSharedMemorySize, 131072);

    zero_cnt_kernel<<<(NGRP * NT + 255) / 256, 256>>>();
    flipflop_main<<<NGRP * NSLICE, THREADS, 131072>>>(inputs, Wv, Pv, b_v, Wz, Pz, b_z, hidden);
    fc_kernel<<<NB * NT / 8, 256>>>(hidden, fcW, fcb, out);
}

// round 4
// speedup vs baseline: 1.6467x; 1.6467x over previous
#include <cuda_runtime.h>

#define NB 128
#define NT 1024
#define ND 3
#define NH 512
#define NC 3
#define NSLICE 16      // h-slices per batch group (CTAs that must sync)
#define HS 32          // h per slice
#define NGRP 8         // batch groups
#define BGr 16         // batch rows per group
#define KS 32          // k per k-slice (per warp)
#define NKS 16         // k-slices = warps
#define THREADS 512

typedef unsigned long long u64;

// per-(group, step) arrival counters; zeroed by zero_cnt_kernel every launch
__device__ int g_cnt[NGRP * NT];

static __device__ __forceinline__ u64 pack2(float x, float y) {
    u64 v; asm("mov.b64 %0, {%1, %2};" : "=l"(v) : "f"(x), "f"(y)); return v;
}
static __device__ __forceinline__ float2 unpack2(u64 v) {
    float2 f; asm("mov.b64 {%0, %1}, %2;" : "=f"(f.x), "=f"(f.y) : "l"(v)); return f;
}
static __device__ __forceinline__ u64 ffma2(u64 a, u64 b, u64 c) {
    u64 d; asm("fma.rn.f32x2 %0, %1, %2, %3;" : "=l"(d) : "l"(a), "l"(b), "l"(c)); return d;
}
static __device__ __forceinline__ u64 fadd2(u64 a, u64 b) {
    u64 d; asm("add.rn.f32x2 %0, %1, %2;" : "=l"(d) : "l"(a), "l"(b)); return d;
}

__global__ void zero_cnt_kernel() {
    int i = blockIdx.x * blockDim.x + threadIdx.x;
    if (i < NGRP * NT) g_cnt[i] = 0;
}

__global__ void nop_kernel() {}   // pads launch period to 4 so ncu (-s 5 -c 1) lands on main

extern __shared__ u64 smem_u64[];

// Persistent recurrence kernel.
// blockIdx: grp = bid/16 (batch group of 16 rows), slice = bid%16 (h-slice of 32).
// Thread roles:
//   compute phase: (ks = tid>>5, hh = tid&31) — warp owns k-slice, lane owns h.
//                  Weights (Wz,W) interleaved pairs live in 64 registers/thread.
//   reduce phase:  (rb = tid>>5, hh = tid&31) — thread owns output (batch rb, h hh).
__global__ void __launch_bounds__(THREADS, 1)
flipflop_main(const float* __restrict__ inputs,
              const float* __restrict__ Wv,
              const float* __restrict__ Pv,
              const float* __restrict__ bv,
              const float* __restrict__ Wz,
              const float* __restrict__ Pz,
              const float* __restrict__ bz,
              float* __restrict__ hidden)
{
    u64* r2   = smem_u64;               // [BGr*NH]  r duplicated pairs (r,r)  = 64 KB
    u64* psum = smem_u64 + BGr * NH;    // [BGr*NKS*HS] partial (z,v) sums     = 64 KB

    const int tid   = threadIdx.x;
    const int grp   = blockIdx.x >> 4;
    const int slice = blockIdx.x & 15;
    const int ks    = tid >> 5;
    const int hh    = tid & 31;
    const int hg    = slice * HS + hh;       // global h for this lane
    const int gb    = grp * BGr;             // first global batch row of group

    // ---- load this thread's weight slice into registers (interleaved z/v) ----
    u64 w[KS];
    {
        const float4* wzr = (const float4*)(Wz + (size_t)hg * NH + ks * KS);
        const float4* wvr = (const float4*)(Wv + (size_t)hg * NH + ks * KS);
        #pragma unroll
        for (int j = 0; j < 8; ++j) {
            float4 az = wzr[j], av = wvr[j];
            w[j*4+0] = pack2(az.x, av.x);
            w[j*4+1] = pack2(az.y, av.y);
            w[j*4+2] = pack2(az.z, av.z);
            w[j*4+3] = pack2(az.w, av.w);
        }
    }

    // ---- reduce-role constants ----
    const int rb = tid >> 5;   // batch row within group (reduce/epilogue role)
    const float pz0 = Pz[hg*3+0], pz1 = Pz[hg*3+1], pz2 = Pz[hg*3+2];
    float pm0 = 0.f, pm1 = 0.f, pm2 = 0.f;        // P_m: bottom half zeroed
    if (hg < NH/2) { pm0 = Pv[hg*3+0]; pm1 = Pv[hg*3+1]; pm2 = Pv[hg*3+2]; }
    const float bzr = bz[hg];
    const float bvr = bv[hg];

    // r0 = 0
    for (int i = tid; i < BGr * NH; i += THREADS) r2[i] = 0ull;
    __syncthreads();

    const float* xrow = inputs + (size_t)(gb + rb) * NT * ND;
    float*       hrow = hidden + (size_t)(gb + rb) * NT * NH;

    for (int t = 0; t < NT; ++t) {
        // prefetch x_t for this thread's reduce row (latency hidden by compute)
        const float x0 = xrow[t*3+0], x1 = xrow[t*3+1], x2 = xrow[t*3+2];

        // ---- compute: partial (z,v) dot-products over this warp's k-slice ----
        #pragma unroll 1
        for (int b = 0; b < BGr; ++b) {
            const u64* rbv = r2 + b * NH + ks * KS;
            u64 a0 = 0ull, a1 = 0ull;
            #pragma unroll
            for (int kk = 0; kk < 16; ++kk) {
                ulonglong2 rv = *(const ulonglong2*)(rbv + kk * 2);   // (r,r),(r,r)
                a0 = ffma2(rv.x, w[kk*2+0], a0);
                a1 = ffma2(rv.y, w[kk*2+1], a1);
            }
            psum[(b * NKS + ks) * HS + hh] = fadd2(a0, a1);
        }
        __syncthreads();

        // ---- reduce + gates: thread owns (rb, hg) ----
        float sz = 0.f, sv = 0.f;
        #pragma unroll
        for (int k = 0; k < NKS; ++k) {
            float2 p = unpack2(psum[(rb * NKS + k) * HS + hh]);
            sz += p.x; sv += p.y;
        }
        const float az = sz + x0*pz0 + x1*pz1 + x2*pz2 + bzr;
        const float av = sv + x0*pm0 + x1*pm1 + x2*pm2 + bvr;
        const float z  = 1.f / (1.f + __expf(-az));
        const float c  = 1.f / (1.f + __expf(-av));
        const float ro = unpack2(r2[rb * NH + hg]).x;
        const float rn = fmaf(z, c - ro, ro);
        hrow[(size_t)t * NH + hg] = rn;        // output AND cross-CTA exchange

        if (t + 1 < NT) {
            // cross-CTA barrier: syncthreads (CTA-level HB) -> single-thread
            // release-arrive carries all threads' stores (fence cumulativity);
            // acquire-poll + syncthreads broadcasts visibility to all threads.
            __syncthreads();
            if (tid == 0) {
                int* pc = &g_cnt[grp * NT + t];
                asm volatile("red.release.gpu.global.add.s32 [%0], 1;"
                             :: "l"(pc) : "memory");
                int v;
                do {
                    asm volatile("ld.acquire.gpu.global.s32 %0, [%1];"
                                 : "=r"(v) : "l"(pc) : "memory");
                } while (v < NSLICE);
            }
            __syncthreads();
            // reload full r(t) (all 16 slices) from hidden, store duplicated
            {
                const float4* src = (const float4*)(hidden + ((size_t)(gb + rb) * NT + t) * NH);
                #pragma unroll
                for (int j = 0; j < 4; ++j) {
                    const int p4 = hh + j * 32;
                    float4 v = src[p4];
                    u64* dst = r2 + rb * NH + p4 * 4;
                    dst[0] = pack2(v.x, v.x);
                    dst[1] = pack2(v.y, v.y);
                    dst[2] = pack2(v.z, v.z);
                    dst[3] = pack2(v.w, v.w);
                }
            }
            __syncthreads();
        }
    }
}

// out[b,t,:] = hidden[b,t,:] @ fc_W^T + fc_b   (memory-bound, ~256 MB read)
__global__ void fc_kernel(const float* __restrict__ hidden,
                          const float* __restrict__ fcW,
                          const float* __restrict__ fcb,
                          float* __restrict__ out)
{
    __shared__ float4 fw[NC][NH/4];
    __shared__ float  fb[4];
    const int tid = threadIdx.x;
    for (int i = tid; i < NC * NH / 4; i += blockDim.x)
        ((float4*)fw)[i] = ((const float4*)fcW)[i];
    if (tid < NC) fb[tid] = fcb[tid];
    __syncthreads();

    const int lane = tid & 31;
    const size_t row = (size_t)blockIdx.x * 8 + (tid >> 5);   // row in [0, B*T)
    const float4* hp = (const float4*)(hidden + row * NH);

    float a0 = 0.f, a1 = 0.f, a2 = 0.f;
    #pragma unroll
    for (int j = 0; j < 4; ++j) {
        const int i = lane + j * 32;
        float4 h4 = hp[i];
        float4 w0 = fw[0][i], w1 = fw[1][i], w2 = fw[2][i];
        a0 += h4.x*w0.x + h4.y*w0.y + h4.z*w0.z + h4.w*w0.w;
        a1 += h4.x*w1.x + h4.y*w1.y + h4.z*w1.z + h4.w*w1.w;
        a2 += h4.x*w2.x + h4.y*w2.y + h4.z*w2.z + h4.w*w2.w;
    }
    #pragma unroll
    for (int o = 16; o; o >>= 1) {
        a0 += __shfl_down_sync(0xffffffffu, a0, o);
        a1 += __shfl_down_sync(0xffffffffu, a1, o);
        a2 += __shfl_down_sync(0xffffffffu, a2, o);
    }
    if (lane == 0) {
        out[row * 3 + 0] = a0 + fb[0];
        out[row * 3 + 1] = a1 + fb[1];
        out[row * 3 + 2] = a2 + fb[2];
    }
}

extern "C" void kernel_launch(void* const* d_in, const int* in_sizes, int n_in,
                              void* d_out, int out_size)
{
    const float* inputs = (const float*)d_in[0];
    const float* Wv     = (const float*)d_in[1];
    const float* Pv     = (const float*)d_in[2];
    const float* b_v    = (const float*)d_in[3];
    const float* Wz     = (const float*)d_in[4];
    const float* Pz     = (const float*)d_in[5];
    const float* b_z    = (const float*)d_in[6];
    const float* fcW    = (const float*)d_in[7];
    const float* fcb    = (const float*)d_in[8];

    // outputs concatenated in reference return order: out (B,T,C) then hidden (B,T,H)
    float* out    = (float*)d_out;
    float* hidden = out + (size_t)NB * NT * NC;

    cudaFuncSetAttribute(flipflop_main,
                         cudaFuncAttributeMaxDynamicSharedMemorySize, 131072);

    zero_cnt_kernel<<<(NGRP * NT + 255) / 256, 256>>>();
    flipflop_main<<<NGRP * NSLICE, THREADS, 131072>>>(inputs, Wv, Pv, b_v, Wz, Pz, b_z, hidden);
    fc_kernel<<<NB * NT / 8, 256>>>(hidden, fcW, fcb, out);
    nop_kernel<<<1, 32>>>();   // keeps launch period = 4 -> ncu skip-5 lands on flipflop_main
}

// round 5
// speedup vs baseline: 1.9436x; 1.1803x over previous
#include <cuda_runtime.h>

#define NB 128
#define NT 1024
#define ND 3
#define NH 512
#define NC 3
#define NSLICE 16      // h-slices per batch group (CTAs that must sync)
#define HS 32          // h per slice
#define NGRP 8         // batch groups
#define BGr 16         // batch rows per group
#define KS 32          // k per k-slice (per warp)
#define NKS 16         // k-slices = warps
#define THREADS 512

typedef unsigned long long u64;

// sense-reversing barrier state, one slot per (group, step).
// Zero-initialized at module load; self-restoring across launches:
// cnt returns to 0 each use, flag flips each use (pollers compare to entry value).
__device__ int g_cnt [NGRP * NT];
__device__ int g_flag[NGRP * NT];

static __device__ __forceinline__ u64 pack2(float x, float y) {
    u64 v; asm("mov.b64 %0, {%1, %2};" : "=l"(v) : "f"(x), "f"(y)); return v;
}
static __device__ __forceinline__ float2 unpack2(u64 v) {
    float2 f; asm("mov.b64 {%0, %1}, %2;" : "=f"(f.x), "=f"(f.y) : "l"(v)); return f;
}
static __device__ __forceinline__ u64 ffma2(u64 a, u64 b, u64 c) {
    u64 d; asm("fma.rn.f32x2 %0, %1, %2, %3;" : "=l"(d) : "l"(a), "l"(b), "l"(c)); return d;
}
static __device__ __forceinline__ u64 fadd2(u64 a, u64 b) {
    u64 d; asm("add.rn.f32x2 %0, %1, %2;" : "=l"(d) : "l"(a), "l"(b)); return d;
}

// called by tid 0 only; one slot per (grp, t)
static __device__ __forceinline__ void group_barrier(int slot) {
    int* pc = &g_cnt[slot];
    int* pf = &g_flag[slot];
    int S;
    asm volatile("ld.relaxed.gpu.global.s32 %0, [%1];" : "=r"(S) : "l"(pf));
    int old;
    asm volatile("atom.release.gpu.global.add.s32 %0, [%1], 1;"
                 : "=r"(old) : "l"(pc) : "memory");
    if (old == NSLICE - 1) {
        asm volatile("st.relaxed.gpu.global.s32 [%0], 0;" :: "l"(pc) : "memory");
        asm volatile("st.release.gpu.global.s32 [%0], %1;" :: "l"(pf), "r"(S ^ 1) : "memory");
    } else {
        int v;
        do {
            asm volatile("ld.acquire.gpu.global.s32 %0, [%1];"
                         : "=r"(v) : "l"(pf) : "memory");
        } while (v == S);
    }
}

extern __shared__ float smem_f[];

// Single persistent kernel: recurrence + in-kernel fc epilogue.
// blockIdx: grp = bid/16 (batch group of 16 rows), slice = bid%16 (h-slice of 32).
// compute role: (ks = tid>>5 = k-slice warp, hh = tid&31 = h within slice)
// reduce  role: (rb = tid>>5 = batch row in group, hh = h within slice)
__global__ void __launch_bounds__(THREADS, 1)
flipflop_main(const float* __restrict__ inputs,
              const float* __restrict__ Wv,
              const float* __restrict__ Pv,
              const float* __restrict__ bv,
              const float* __restrict__ Wz,
              const float* __restrict__ Pz,
              const float* __restrict__ bz,
              const float* __restrict__ fcW,
              const float* __restrict__ fcb,
              float* __restrict__ out,
              float* __restrict__ hidden)
{
    float* rS   = smem_f;                     // [BGr*NH] r(t), plain floats   = 32 KB
    u64*   psum = (u64*)(smem_f + BGr * NH);  // [BGr*NKS*HS] partial (z,v)    = 64 KB

    const int tid   = threadIdx.x;
    const int grp   = blockIdx.x >> 4;
    const int slice = blockIdx.x & 15;
    const int ks    = tid >> 5;
    const int hh    = tid & 31;
    const int hg    = slice * HS + hh;        // global h for this lane
    const int gb    = grp * BGr;              // first global batch row of group

    // ---- weight slice into registers: k-pairs, z and v separate ----
    u64 wz[16], wv[16];
    {
        const u64* zr = (const u64*)(Wz + (size_t)hg * NH + ks * KS);
        const u64* vr = (const u64*)(Wv + (size_t)hg * NH + ks * KS);
        #pragma unroll
        for (int j = 0; j < 16; ++j) { wz[j] = zr[j]; wv[j] = vr[j]; }
    }

    // ---- reduce-role constants ----
    const int rb = tid >> 5;
    const float pz0 = Pz[hg*3+0], pz1 = Pz[hg*3+1], pz2 = Pz[hg*3+2];
    float pm0 = 0.f, pm1 = 0.f, pm2 = 0.f;         // P_m: bottom half zeroed
    if (hg < NH/2) { pm0 = Pv[hg*3+0]; pm1 = Pv[hg*3+1]; pm2 = Pv[hg*3+2]; }
    const float bzr = bz[hg];
    const float bvr = bv[hg];

    // r0 = 0
    for (int i = tid; i < BGr * NH; i += THREADS) rS[i] = 0.f;
    __syncthreads();

    const float* xrow = inputs + (size_t)(gb + rb) * NT * ND;
    float*       hrow = hidden + (size_t)(gb + rb) * NT * NH;

    for (int t = 0; t < NT; ++t) {
        const float x0 = xrow[t*3+0], x1 = xrow[t*3+1], x2 = xrow[t*3+2];

        // ---- compute: partial (z,v) dot-products over this warp's k-slice ----
        #pragma unroll 1
        for (int b = 0; b < BGr; ++b) {
            const ulonglong2* rp = (const ulonglong2*)(rS + b * NH + ks * KS);
            u64 az0 = 0ull, az1 = 0ull, av0 = 0ull, av1 = 0ull;
            #pragma unroll
            for (int kk = 0; kk < 8; ++kk) {
                ulonglong2 rr = rp[kk];          // 4 consecutive r values (broadcast)
                az0 = ffma2(rr.x, wz[kk*2+0], az0);
                av0 = ffma2(rr.x, wv[kk*2+0], av0);
                az1 = ffma2(rr.y, wz[kk*2+1], az1);
                av1 = ffma2(rr.y, wv[kk*2+1], av1);
            }
            const float2 fz0 = unpack2(fadd2(az0, az1));
            const float2 fv0 = unpack2(fadd2(av0, av1));
            psum[(b * NKS + ks) * HS + hh] = pack2(fz0.x + fz0.y, fv0.x + fv0.y);
        }
        __syncthreads();

        // ---- reduce + gates: thread owns (rb, hg) ----
        float sz = 0.f, sv = 0.f;
        #pragma unroll
        for (int k = 0; k < NKS; ++k) {
            float2 p = unpack2(psum[(rb * NKS + k) * HS + hh]);
            sz += p.x; sv += p.y;
        }
        const float az = sz + x0*pz0 + x1*pz1 + x2*pz2 + bzr;
        const float av = sv + x0*pm0 + x1*pm1 + x2*pm2 + bvr;
        const float z  = 1.f / (1.f + __expf(-az));
        const float c  = 1.f / (1.f + __expf(-av));
        const float ro = rS[rb * NH + hg];
        const float rn = fmaf(z, c - ro, ro);
        hrow[(size_t)t * NH + hg] = rn;          // output AND cross-CTA exchange

        // cross-CTA sense-reversing barrier (after every step, incl. the last)
        __syncthreads();
        if (tid == 0) group_barrier(grp * NT + t);
        __syncthreads();

        if (t + 1 < NT) {
            // reload full r(t) (all 16 slices) from hidden
            const float4* src = (const float4*)(hidden + ((size_t)(gb + rb) * NT + t) * NH);
            float4*       dst = (float4*)(rS + rb * NH);
            #pragma unroll
            for (int j = 0; j < 4; ++j) dst[hh + j * 32] = src[hh + j * 32];
            __syncthreads();
        }
    }

    // ================= fc epilogue =================
    // group's hidden fully written (last barrier passed). CTA (grp, slice)
    // handles t in [slice*64, slice*64+64) for all 16 batch rows of the group.
    // warp w -> batch row gb+w, lane-parallel over H, shuffle-reduce.
    float* fw = rS;                               // reuse smem (r dead)
    __syncthreads();
    for (int i = tid; i < NC * NH; i += THREADS) fw[i] = fcW[i];
    const float fb0 = fcb[0], fb1 = fcb[1], fb2 = fcb[2];
    __syncthreads();

    // hoist this lane's fc weights into registers
    float w0[4], w1[4], w2[4];
    #pragma unroll
    for (int j = 0; j < 4; ++j) {
        const int i = hh + j * 32;
        w0[j*1] = 0.f; // placate compiler ordering (overwritten below)
        ((float4*)w0)[0] = ((float4*)w0)[0];
    }
    float4 W0[1], W1[1], W2[1];
    float4 fw0[4], fw1[4], fw2[4];
    #pragma unroll
    for (int j = 0; j < 4; ++j) {
        const int i = hh + j * 32;
        fw0[j] = ((const float4*)(fw + 0 * NH))[i];
        fw1[j] = ((const float4*)(fw + 1 * NH))[i];
        fw2[j] = ((const float4*)(fw + 2 * NH))[i];
    }
    (void)W0; (void)W1; (void)W2; (void)w0; (void)w1; (void)w2;

    const int w = tid >> 5;                       // warp = batch row in group
    const int t0 = slice * (NT / NSLICE);
    const float* hp = hidden + ((size_t)(gb + w) * NT + t0) * NH;
    float*       op = out    + ((size_t)(gb + w) * NT + t0) * NC;

    for (int it = 0; it < NT / NSLICE; ++it) {
        const float4* h4 = (const float4*)(hp + (size_t)it * NH);
        float a0 = 0.f, a1 = 0.f, a2 = 0.f;
        #pragma unroll
        for (int j = 0; j < 4; ++j) {
            float4 h = h4[hh + j * 32];
            a0 += h.x*fw0[j].x + h.y*fw0[j].y + h.z*fw0[j].z + h.w*fw0[j].w;
            a1 += h.x*fw1[j].x + h.y*fw1[j].y + h.z*fw1[j].z + h.w*fw1[j].w;
            a2 += h.x*fw2[j].x + h.y*fw2[j].y + h.z*fw2[j].z + h.w*fw2[j].w;
        }
        #pragma unroll
        for (int o = 16; o; o >>= 1) {
            a0 += __shfl_down_sync(0xffffffffu, a0, o);
            a1 += __shfl_down_sync(0xffffffffu, a1, o);
            a2 += __shfl_down_sync(0xffffffffu, a2, o);
        }
        if (hh == 0) {
            op[it*3+0] = a0 + fb0;
            op[it*3+1] = a1 + fb1;
            op[it*3+2] = a2 + fb2;
        }
    }
}

extern "C" void kernel_launch(void* const* d_in, const int* in_sizes, int n_in,
                              void* d_out, int out_size)
{
    const float* inputs = (const float*)d_in[0];
    const float* Wv     = (const float*)d_in[1];
    const float* Pv     = (const float*)d_in[2];
    const float* b_v    = (const float*)d_in[3];
    const float* Wz     = (const float*)d_in[4];
    const float* Pz     = (const float*)d_in[5];
    const float* b_z    = (const float*)d_in[6];
    const float* fcW    = (const float*)d_in[7];
    const float* fcb    = (const float*)d_in[8];

    // outputs concatenated in reference return order: out (B,T,C) then hidden (B,T,H)
    float* out    = (float*)d_out;
    float* hidden = out + (size_t)NB * NT * NC;

    const int smem_bytes = (BGr * NH) * 4 + (BGr * NKS * HS) * 8;   // 32KB + 64KB
    cudaFuncSetAttribute(flipflop_main,
                         cudaFuncAttributeMaxDynamicSharedMemorySize, smem_bytes);

    flipflop_main<<<NGRP * NSLICE, THREADS, smem_bytes>>>(
        inputs, Wv, Pv, b_v, Wz, Pz, b_z, fcW, fcb, out, hidden);
}